// round 6
// baseline (speedup 1.0000x reference)
#include <cuda_runtime.h>
#include <math.h>
#include <stdint.h>

// ---------------------------------------------------------------------------
// Problem constants
// ---------------------------------------------------------------------------
#define HID    4096
#define SEQ    2048
#define BATCH  2
#define NHEADS 32
#define NKV    8
#define HD     128
#define KVW    (NKV * HD)        // 1024
#define MROWS  (BATCH * SEQ)     // 4096

// ---------------------------------------------------------------------------
// Scratch (device globals: no allocation allowed)
// ---------------------------------------------------------------------------
__device__ float g_Q[(size_t)MROWS * HID];
__device__ float g_K[(size_t)MROWS * KVW];
__device__ float g_V[(size_t)MROWS * KVW];
__device__ float g_A[(size_t)MROWS * HID];
__device__ float g_X[(size_t)MROWS * HID];
__device__ float g_Wq[(size_t)HID * HID];
__device__ float g_Wk[(size_t)HID * KVW];
__device__ float g_Wv[(size_t)HID * KVW];
__device__ float g_Wo[(size_t)HID * HID];

// ---------------------------------------------------------------------------
// tf32 helpers
// ---------------------------------------------------------------------------
__device__ __forceinline__ float to_tf32(float x) {
    uint32_t r;
    asm("cvt.rna.tf32.f32 %0, %1;" : "=r"(r) : "f"(x));
    return __uint_as_float(r);
}
__device__ __forceinline__ uint32_t fau(float x) { return __float_as_uint(x); }

__global__ void round_tf32_kernel(const float* __restrict__ in,
                                  float* __restrict__ out, int n4)
{
    int i = blockIdx.x * blockDim.x + threadIdx.x;
    if (i >= n4) return;
    float4 v = ((const float4*)in)[i];
    v.x = to_tf32(v.x); v.y = to_tf32(v.y);
    v.z = to_tf32(v.z); v.w = to_tf32(v.w);
    ((float4*)out)[i] = v;
}

// fast exp2 on the fma/alu pipes
__device__ __forceinline__ float exp2p(float x) {
    x = fmaxf(x, -126.f);
    float t = x + 12582912.f;
    float n = t - 12582912.f;
    float f = x - n;
    float p = 1.5403530e-4f;
    p = fmaf(p, f, 1.3333558e-3f);
    p = fmaf(p, f, 9.6181291e-3f);
    p = fmaf(p, f, 5.5504109e-2f);
    p = fmaf(p, f, 2.4022651e-1f);
    p = fmaf(p, f, 6.9314718e-1f);
    p = fmaf(p, f, 1.0f);
    float sc = __int_as_float(0x3f800000 + (__float_as_int(t) << 23));
    return p * sc;
}

__device__ __forceinline__ void mma_tf32(float* c, uint32_t a0, uint32_t a1,
                                         uint32_t a2, uint32_t a3,
                                         uint32_t b0, uint32_t b1)
{
    asm volatile(
        "mma.sync.aligned.m16n8k8.row.col.f32.tf32.tf32.f32 "
        "{%0,%1,%2,%3}, {%4,%5,%6,%7}, {%8,%9}, {%0,%1,%2,%3};\n"
        : "+f"(c[0]), "+f"(c[1]), "+f"(c[2]), "+f"(c[3])
        : "r"(a0), "r"(a1), "r"(a2), "r"(a3), "r"(b0), "r"(b1));
}

__device__ __forceinline__ void cp16(uint32_t dst, const float* src) {
    asm volatile("cp.async.cg.shared.global [%0], [%1], 16;\n"
                 :: "r"(dst), "l"(src));
}
#define CP_COMMIT() asm volatile("cp.async.commit_group;\n" ::: "memory")
#define CP_WAIT1()  asm volatile("cp.async.wait_group 1;\n" ::: "memory")
#define CP_WAIT0()  asm volatile("cp.async.wait_group 0;\n" ::: "memory")

// ---------------------------------------------------------------------------
// TF32 tensor-core GEMM: C[M,N] = A[M,K] @ B[K,N].
// 256x128x32 CTA tile, 256 threads (8 warps, 4x2), warp tile 64x64,
// 3-stage cp.async ring, ONE syncthreads per k-chunk.
// ---------------------------------------------------------------------------
#define BM 256
#define BN 128
#define BK 32
#define AST 36
#define BST 136
#define GSTG 3
#define GEMM_SMEM ((GSTG * BM * AST + GSTG * BK * BST) * 4)   // 162816 B

__global__ void __launch_bounds__(256, 1)
tf32gemm(const float* __restrict__ A, const float* __restrict__ B,
         float* __restrict__ C, int M, int N, int K, int round_out)
{
    extern __shared__ float sm[];
    float* As = sm;                         // [GSTG][BM][AST]
    float* Bs = sm + GSTG * BM * AST;       // [GSTG][BK][BST]

    const int tid  = threadIdx.x;
    const int warp = tid >> 5;
    const int lane = tid & 31;
    const int wm = warp >> 1;               // 0..3
    const int wn = warp & 1;                // 0..1
    const int g  = lane >> 2;
    const int tg = lane & 3;
    const int bm = blockIdx.y * BM;
    const int bn = blockIdx.x * BN;

    float acc[4][8][4];
#pragma unroll
    for (int mi = 0; mi < 4; mi++)
#pragma unroll
        for (int ni = 0; ni < 8; ni++)
#pragma unroll
            for (int r = 0; r < 4; r++) acc[mi][ni][r] = 0.f;

    const int T = K / BK;

    auto issue = [&](int t, int buf) {
        const float* Ag = A + (size_t)bm * K + t * BK;
        float* Asb = As + buf * BM * AST;
#pragma unroll
        for (int u = 0; u < 8; u++) {       // 256x32 = 2048 float4
            int i4 = tid + 256 * u;
            int r = i4 >> 3, c4 = i4 & 7;
            uint32_t d = (uint32_t)__cvta_generic_to_shared(Asb + r * AST + c4 * 4);
            cp16(d, Ag + (size_t)r * K + c4 * 4);
        }
        const float* Bg = B + (size_t)(t * BK) * N + bn;
        float* Bsb = Bs + buf * BK * BST;
#pragma unroll
        for (int u = 0; u < 4; u++) {       // 32x128 = 1024 float4
            int i4 = tid + 256 * u;
            int r = i4 >> 5, c4 = i4 & 31;
            uint32_t d = (uint32_t)__cvta_generic_to_shared(Bsb + r * BST + c4 * 4);
            cp16(d, Bg + (size_t)r * N + c4 * 4);
        }
        CP_COMMIT();
    };

    issue(0, 0);
    issue(1, 1);

    for (int t = 0; t < T; t++) {
        if (t + 1 < T) CP_WAIT1(); else CP_WAIT0();
        __syncthreads();
        if (t + 2 < T) issue(t + 2, (t + 2) % GSTG);

        const float* Ab = As + (t % GSTG) * BM * AST;
        const float* Bb = Bs + (t % GSTG) * BK * BST;

#pragma unroll
        for (int ks = 0; ks < 4; ks++) {
            const int kc = ks * 8;
            uint32_t a[4][4], b[8][2];
#pragma unroll
            for (int mi = 0; mi < 4; mi++) {
                int row = wm * 64 + mi * 16 + g;
                a[mi][0] = fau(Ab[row * AST + kc + tg]);
                a[mi][1] = fau(Ab[(row + 8) * AST + kc + tg]);
                a[mi][2] = fau(Ab[row * AST + kc + tg + 4]);
                a[mi][3] = fau(Ab[(row + 8) * AST + kc + tg + 4]);
            }
#pragma unroll
            for (int ni = 0; ni < 8; ni++) {
                int col = wn * 64 + ni * 8 + g;
                b[ni][0] = fau(Bb[(kc + tg) * BST + col]);
                b[ni][1] = fau(Bb[(kc + tg + 4) * BST + col]);
            }
#pragma unroll
            for (int mi = 0; mi < 4; mi++)
#pragma unroll
                for (int ni = 0; ni < 8; ni++)
                    mma_tf32(acc[mi][ni], a[mi][0], a[mi][1], a[mi][2], a[mi][3],
                             b[ni][0], b[ni][1]);
        }
    }

#pragma unroll
    for (int mi = 0; mi < 4; mi++) {
        int row0 = bm + wm * 64 + mi * 16 + g;
#pragma unroll
        for (int ni = 0; ni < 8; ni++) {
            int col = bn + wn * 64 + ni * 8 + tg * 2;
            float4 v = make_float4(acc[mi][ni][0], acc[mi][ni][1],
                                   acc[mi][ni][2], acc[mi][ni][3]);
            if (round_out) {
                v.x = to_tf32(v.x); v.y = to_tf32(v.y);
                v.z = to_tf32(v.z); v.w = to_tf32(v.w);
            }
            *(float2*)(C + (size_t)row0 * N + col) = make_float2(v.x, v.y);
            *(float2*)(C + (size_t)(row0 + 8) * N + col) = make_float2(v.z, v.w);
        }
    }
}

// ---------------------------------------------------------------------------
// RoPE (in-place, pair-safe), rounds outputs to tf32.
// ---------------------------------------------------------------------------
__global__ void rope_kernel(float* __restrict__ T, const int* __restrict__ pos_ids,
                            int cols, int npairs)
{
    int idx = blockIdx.x * blockDim.x + threadIdx.x;
    if (idx >= npairs) return;
    int half = cols >> 1;
    int row = idx / half;
    int cp = idx - row * half;
    int h = cp >> 6;
    int d = cp & 63;
    int c0 = h * 128 + d;
    float pos = (float)pos_ids[row];
    double inv = pow(10000.0, -((double)d) / 64.0);
    float ang = (float)((double)pos * inv);
    float sn = sinf(ang), cs = cosf(ang);
    float* rowp = T + (size_t)row * cols;
    float x0 = rowp[c0];
    float x1 = rowp[c0 + 64];
    rowp[c0]      = to_tf32(x0 * cs - x1 * sn);
    rowp[c0 + 64] = to_tf32(x1 * cs + x0 * sn);
}

// ---------------------------------------------------------------------------
// Tensor-core flash attention (causal, GQA), tf32 mma.sync.
// CTA = 128 q rows x head x batch; 8 warps x 16 rows; K-tile 32.
// 3-buffer cp.async ring, ONE syncthreads/iter; Q fragments in registers.
// ---------------------------------------------------------------------------
#define FQ   128
#define FKT  32
#define FSTG 3
#define QST  132
#define KST  132
#define VST  136
#define PST2 36

#define OFF_Q 0
#define OFF_K (OFF_Q + FQ * QST)
#define OFF_V (OFF_K + FSTG * FKT * KST)
#define OFF_P (OFF_V + FSTG * FKT * VST)
#define OFF_M (OFF_P + FQ * PST2)
#define FL_SMEM ((OFF_M + FSTG * FKT) * 4)     // 189312 B

#define SCL 0.12751743f   // (1/sqrt(128)) * log2(e)

__global__ void __launch_bounds__(256, 1)
flash_tc(const float* __restrict__ Q, const float* __restrict__ K,
         const float* __restrict__ V, const float* __restrict__ amask,
         float* __restrict__ Oc)
{
    extern __shared__ float sm[];
    float* Qs  = sm + OFF_Q;
    float* Ks  = sm + OFF_K;
    float* Vs  = sm + OFF_V;
    float* Ps  = sm + OFF_P;
    float* kmb = sm + OFF_M;

    const int hb = blockIdx.x;
    const int h = hb & 31, b = hb >> 5;
    const int qb = gridDim.y - 1 - blockIdx.y;     // heavy q-blocks first
    const int q0 = qb * FQ;
    const int tid = threadIdx.x;
    const int w = tid >> 5, lane = tid & 31;
    const int g = lane >> 2, tg = lane & 3;
    const int kvh = h >> 2;
    const int myrowmax = q0 + w * 16 + 15;

    float oacc[16][4];
#pragma unroll
    for (int nt = 0; nt < 16; nt++)
#pragma unroll
        for (int r = 0; r < 4; r++) oacc[nt][r] = 0.f;
    float m2[2] = {-1e9f, -1e9f}, l2[2] = {0.f, 0.f};

    auto issue = [&](int t, int buf) {
        const float* Kg = K + (size_t)(b * SEQ + t * FKT) * KVW + kvh * HD;
        const float* Vg = V + (size_t)(b * SEQ + t * FKT) * KVW + kvh * HD;
#pragma unroll
        for (int u = 0; u < 4; u++) {
            int i4 = tid + 256 * u;
            int r = i4 >> 5, c4 = i4 & 31;
            uint32_t dk = (uint32_t)__cvta_generic_to_shared(
                Ks + buf * FKT * KST + r * KST + c4 * 4);
            cp16(dk, Kg + (size_t)r * KVW + c4 * 4);
            uint32_t dv = (uint32_t)__cvta_generic_to_shared(
                Vs + buf * FKT * VST + r * VST + c4 * 4);
            cp16(dv, Vg + (size_t)r * KVW + c4 * 4);
        }
        if (tid < FKT)
            kmb[buf * FKT + tid] =
                (amask[b * SEQ + t * FKT + tid] > 0.f) ? 0.f : -1e9f;
        CP_COMMIT();
    };

    // Q tile -> smem (plain stores)
    const float* Qg = Q + (size_t)(b * SEQ + q0) * HID + h * HD;
#pragma unroll
    for (int u = 0; u < 16; u++) {
        int i4 = tid + 256 * u;
        int r = i4 >> 5, c4 = i4 & 31;
        float4 v = *(const float4*)(Qg + (size_t)r * HID + c4 * 4);
        Qs[r * QST + c4 * 4 + 0] = v.x;
        Qs[r * QST + c4 * 4 + 1] = v.y;
        Qs[r * QST + c4 * 4 + 2] = v.z;
        Qs[r * QST + c4 * 4 + 3] = v.w;
    }

    const int T = 4 * (qb + 1);    // T >= 4
    issue(0, 0);
    issue(1, 1);
    __syncthreads();               // Q visible; prefetch in flight

    // Q fragments -> registers (64 regs), removes Q LDS from the hot loop
    uint32_t qa[16][4];
    {
        const float* Qw = Qs + (w * 16) * QST;
#pragma unroll
        for (int ks = 0; ks < 16; ks++) {
            const int kc = ks * 8;
            qa[ks][0] = fau(Qw[g * QST + kc + tg]);
            qa[ks][1] = fau(Qw[(g + 8) * QST + kc + tg]);
            qa[ks][2] = fau(Qw[g * QST + kc + tg + 4]);
            qa[ks][3] = fau(Qw[(g + 8) * QST + kc + tg + 4]);
        }
    }

    const float* Pw = Ps + (w * 16) * PST2;

    for (int t = 0; t < T; t++) {
        const int buf = t % FSTG;
        if (t + 1 < T) CP_WAIT1(); else CP_WAIT0();
        __syncthreads();
        if (t + 2 < T) issue(t + 2, (t + 2) % FSTG);

        const int k0 = t * FKT;
        if (k0 > myrowmax) continue;            // fully masked for this warp

        // ---- S = Q @ K^T ----
        float sacc[4][4];
#pragma unroll
        for (int nt = 0; nt < 4; nt++)
#pragma unroll
            for (int r = 0; r < 4; r++) sacc[nt][r] = 0.f;

        const float* Kb = Ks + buf * FKT * KST;
#pragma unroll
        for (int ks = 0; ks < 16; ks++) {
            const int kc = ks * 8;
#pragma unroll
            for (int nt = 0; nt < 4; nt++) {
                uint32_t b0 = fau(Kb[(nt * 8 + g) * KST + kc + tg]);
                uint32_t b1 = fau(Kb[(nt * 8 + g) * KST + kc + tg + 4]);
                mma_tf32(sacc[nt], qa[ks][0], qa[ks][1], qa[ks][2], qa[ks][3],
                         b0, b1);
            }
        }

        // ---- mask + scale into exp2 domain ----
        const int rowg0 = q0 + w * 16 + g;
        const int rowg1 = rowg0 + 8;
#pragma unroll
        for (int nt = 0; nt < 4; nt++) {
            int cl = nt * 8 + 2 * tg;
            int c0 = k0 + cl;
            float kb0 = kmb[buf * FKT + cl];
            float kb1 = kmb[buf * FKT + cl + 1];
            sacc[nt][0] = (c0     <= rowg0) ? sacc[nt][0] * SCL + kb0 : -1e9f;
            sacc[nt][1] = (c0 + 1 <= rowg0) ? sacc[nt][1] * SCL + kb1 : -1e9f;
            sacc[nt][2] = (c0     <= rowg1) ? sacc[nt][2] * SCL + kb0 : -1e9f;
            sacc[nt][3] = (c0 + 1 <= rowg1) ? sacc[nt][3] * SCL + kb1 : -1e9f;
        }

        // ---- online softmax (exp2 domain) ----
#pragma unroll
        for (int r = 0; r < 2; r++) {
            float pm = -1e30f;
#pragma unroll
            for (int nt = 0; nt < 4; nt++)
                pm = fmaxf(pm, fmaxf(sacc[nt][2 * r], sacc[nt][2 * r + 1]));
            pm = fmaxf(pm, __shfl_xor_sync(0xffffffffu, pm, 1));
            pm = fmaxf(pm, __shfl_xor_sync(0xffffffffu, pm, 2));
            float mn = fmaxf(m2[r], pm);
            float al = exp2p(m2[r] - mn);
            m2[r] = mn;
            float rs = 0.f;
            float* prow = Ps + (w * 16 + g + 8 * r) * PST2;
#pragma unroll
            for (int nt = 0; nt < 4; nt++) {
                float p0 = exp2p(sacc[nt][2 * r] - mn);
                float p1 = exp2p(sacc[nt][2 * r + 1] - mn);
                rs += p0 + p1;
                *(float2*)(prow + nt * 8 + 2 * tg) =
                    make_float2(to_tf32(p0), to_tf32(p1));
            }
            rs += __shfl_xor_sync(0xffffffffu, rs, 1);
            rs += __shfl_xor_sync(0xffffffffu, rs, 2);
            l2[r] = l2[r] * al + rs;
            if (al != 1.f) {
#pragma unroll
                for (int nt = 0; nt < 16; nt++) {
                    oacc[nt][2 * r]     *= al;
                    oacc[nt][2 * r + 1] *= al;
                }
            }
        }
        __syncwarp();

        // ---- O += P @ V ----
        const float* Vb = Vs + buf * FKT * VST;
#pragma unroll
        for (int ks = 0; ks < 4; ks++) {
            const int kc = ks * 8;
            uint32_t a0 = fau(Pw[g * PST2 + kc + tg]);
            uint32_t a1 = fau(Pw[(g + 8) * PST2 + kc + tg]);
            uint32_t a2 = fau(Pw[g * PST2 + kc + tg + 4]);
            uint32_t a3 = fau(Pw[(g + 8) * PST2 + kc + tg + 4]);
#pragma unroll
            for (int nt = 0; nt < 16; nt++) {
                uint32_t b0 = fau(Vb[(kc + tg) * VST + nt * 8 + g]);
                uint32_t b1 = fau(Vb[(kc + tg + 4) * VST + nt * 8 + g]);
                mma_tf32(oacc[nt], a0, a1, a2, a3, b0, b1);
            }
        }
    }

    // ---- epilogue ----
    float i0 = 1.f / l2[0], i1 = 1.f / l2[1];
    size_t ro0 = (size_t)(b * SEQ + q0 + w * 16 + g) * HID + h * HD;
    size_t ro1 = ro0 + (size_t)8 * HID;
#pragma unroll
    for (int nt = 0; nt < 16; nt++) {
        int c = nt * 8 + 2 * tg;
        *(float2*)(Oc + ro0 + c) = make_float2(to_tf32(oacc[nt][0] * i0),
                                               to_tf32(oacc[nt][1] * i0));
        *(float2*)(Oc + ro1 + c) = make_float2(to_tf32(oacc[nt][2] * i1),
                                               to_tf32(oacc[nt][3] * i1));
    }
}

// ---------------------------------------------------------------------------
// Launch
// ---------------------------------------------------------------------------
extern "C" void kernel_launch(void* const* d_in, const int* in_sizes, int n_in,
                              void* d_out, int out_size)
{
    const float* hs    = (const float*)d_in[0];
    const float* amask = (const float*)d_in[1];
    const int*   pos   = (const int*)d_in[2];
    const float* Wq    = (const float*)d_in[3];
    const float* Wk    = (const float*)d_in[4];
    const float* Wv    = (const float*)d_in[5];
    const float* Wo    = (const float*)d_in[6];
    float* out = (float*)d_out;

    float *Qp, *Kp, *Vp, *Ap, *Xp, *Wqp, *Wkp, *Wvp, *Wop;
    cudaGetSymbolAddress((void**)&Qp, g_Q);
    cudaGetSymbolAddress((void**)&Kp, g_K);
    cudaGetSymbolAddress((void**)&Vp, g_V);
    cudaGetSymbolAddress((void**)&Ap, g_A);
    cudaGetSymbolAddress((void**)&Xp, g_X);
    cudaGetSymbolAddress((void**)&Wqp, g_Wq);
    cudaGetSymbolAddress((void**)&Wkp, g_Wk);
    cudaGetSymbolAddress((void**)&Wvp, g_Wv);
    cudaGetSymbolAddress((void**)&Wop, g_Wo);

    cudaFuncSetAttribute(tf32gemm, cudaFuncAttributeMaxDynamicSharedMemorySize,
                         GEMM_SMEM);
    cudaFuncSetAttribute(flash_tc, cudaFuncAttributeMaxDynamicSharedMemorySize,
                         FL_SMEM);

    // Round inputs to tf32 (RNA)
    {
        int n;
        n = MROWS * HID / 4;
        round_tf32_kernel<<<(n + 255) / 256, 256>>>(hs, Xp, n);
        n = HID * HID / 4;
        round_tf32_kernel<<<(n + 255) / 256, 256>>>(Wq, Wqp, n);
        round_tf32_kernel<<<(n + 255) / 256, 256>>>(Wo, Wop, n);
        n = HID * KVW / 4;
        round_tf32_kernel<<<(n + 255) / 256, 256>>>(Wk, Wkp, n);
        round_tf32_kernel<<<(n + 255) / 256, 256>>>(Wv, Wvp, n);
    }

    // Projections (tf32 tensor cores); outputs rounded to tf32
    tf32gemm<<<dim3(HID / BN, MROWS / BM), 256, GEMM_SMEM>>>(Xp, Wqp, Qp, MROWS, HID, HID, 1);
    tf32gemm<<<dim3(KVW / BN, MROWS / BM), 256, GEMM_SMEM>>>(Xp, Wkp, Kp, MROWS, KVW, HID, 1);
    tf32gemm<<<dim3(KVW / BN, MROWS / BM), 256, GEMM_SMEM>>>(Xp, Wvp, Vp, MROWS, KVW, HID, 1);

    // RoPE on Q and K
    {
        int npq = MROWS * (HID / 2);
        rope_kernel<<<(npq + 255) / 256, 256>>>(Qp, pos, HID, npq);
        int npk = MROWS * (KVW / 2);
        rope_kernel<<<(npk + 255) / 256, 256>>>(Kp, pos, KVW, npk);
    }

    // Tensor-core flash attention
    flash_tc<<<dim3(NHEADS * BATCH, SEQ / FQ), 256, FL_SMEM>>>(Qp, Kp, Vp,
                                                               amask, Ap);

    // Output projection, full fp32 output
    tf32gemm<<<dim3(HID / BN, MROWS / BM), 256, GEMM_SMEM>>>(Ap, Wop, out, MROWS, HID, HID, 0);
}

// round 7
// speedup vs baseline: 1.1880x; 1.1880x over previous
#include <cuda_runtime.h>
#include <math.h>
#include <stdint.h>

// ---------------------------------------------------------------------------
// Problem constants
// ---------------------------------------------------------------------------
#define HID    4096
#define SEQ    2048
#define BATCH  2
#define NHEADS 32
#define NKV    8
#define HD     128
#define KVW    (NKV * HD)        // 1024
#define MROWS  (BATCH * SEQ)     // 4096

// ---------------------------------------------------------------------------
// Scratch (device globals: no allocation allowed)
// ---------------------------------------------------------------------------
__device__ float g_Q[(size_t)MROWS * HID];
__device__ float g_K[(size_t)MROWS * KVW];
__device__ float g_V[(size_t)MROWS * KVW];
__device__ float g_A[(size_t)MROWS * HID];
__device__ float g_X[(size_t)MROWS * HID];
__device__ float g_Wq[(size_t)HID * HID];
__device__ float g_Wk[(size_t)HID * KVW];
__device__ float g_Wv[(size_t)HID * KVW];
__device__ float g_Wo[(size_t)HID * HID];

// ---------------------------------------------------------------------------
// tf32 helpers
// ---------------------------------------------------------------------------
__device__ __forceinline__ float to_tf32(float x) {
    uint32_t r;
    asm("cvt.rna.tf32.f32 %0, %1;" : "=r"(r) : "f"(x));
    return __uint_as_float(r);
}
__device__ __forceinline__ uint32_t fau(float x) { return __float_as_uint(x); }

__global__ void round_tf32_kernel(const float* __restrict__ in,
                                  float* __restrict__ out, int n4)
{
    int i = blockIdx.x * blockDim.x + threadIdx.x;
    if (i >= n4) return;
    float4 v = ((const float4*)in)[i];
    v.x = to_tf32(v.x); v.y = to_tf32(v.y);
    v.z = to_tf32(v.z); v.w = to_tf32(v.w);
    ((float4*)out)[i] = v;
}

// fast exp2 on the fma/alu pipes
__device__ __forceinline__ float exp2p(float x) {
    x = fmaxf(x, -126.f);
    float t = x + 12582912.f;
    float n = t - 12582912.f;
    float f = x - n;
    float p = 1.5403530e-4f;
    p = fmaf(p, f, 1.3333558e-3f);
    p = fmaf(p, f, 9.6181291e-3f);
    p = fmaf(p, f, 5.5504109e-2f);
    p = fmaf(p, f, 2.4022651e-1f);
    p = fmaf(p, f, 6.9314718e-1f);
    p = fmaf(p, f, 1.0f);
    float sc = __int_as_float(0x3f800000 + (__float_as_int(t) << 23));
    return p * sc;
}

__device__ __forceinline__ void mma_tf32(float* c, uint32_t a0, uint32_t a1,
                                         uint32_t a2, uint32_t a3,
                                         uint32_t b0, uint32_t b1)
{
    asm volatile(
        "mma.sync.aligned.m16n8k8.row.col.f32.tf32.tf32.f32 "
        "{%0,%1,%2,%3}, {%4,%5,%6,%7}, {%8,%9}, {%0,%1,%2,%3};\n"
        : "+f"(c[0]), "+f"(c[1]), "+f"(c[2]), "+f"(c[3])
        : "r"(a0), "r"(a1), "r"(a2), "r"(a3), "r"(b0), "r"(b1));
}

__device__ __forceinline__ void cp16(uint32_t dst, const float* src) {
    asm volatile("cp.async.cg.shared.global [%0], [%1], 16;\n"
                 :: "r"(dst), "l"(src));
}
#define CP_COMMIT() asm volatile("cp.async.commit_group;\n" ::: "memory")
#define CP_WAIT1()  asm volatile("cp.async.wait_group 1;\n" ::: "memory")
#define CP_WAIT0()  asm volatile("cp.async.wait_group 0;\n" ::: "memory")

// ---------------------------------------------------------------------------
// TF32 tensor-core GEMM (round-4/5 proven config):
// 128x128x32 tile, 128 threads (2x2 warps), 2 CTAs/SM, 2-stage cp.async.
// ---------------------------------------------------------------------------
#define BM 128
#define BN 128
#define BK 32
#define AST 36
#define BST 136
#define GEMM_SMEM ((2 * BM * AST + 2 * BK * BST) * 4)   // 71680 B

__global__ void __launch_bounds__(128, 2)
tf32gemm(const float* __restrict__ A, const float* __restrict__ B,
         float* __restrict__ C, int M, int N, int K, int round_out)
{
    extern __shared__ float sm[];
    float* As = sm;
    float* Bs = sm + 2 * BM * AST;

    const int tid  = threadIdx.x;
    const int warp = tid >> 5;
    const int lane = tid & 31;
    const int wm = warp >> 1;
    const int wn = warp & 1;
    const int g  = lane >> 2;
    const int tg = lane & 3;
    const int bm = blockIdx.y * BM;
    const int bn = blockIdx.x * BN;

    float acc[4][8][4];
#pragma unroll
    for (int mi = 0; mi < 4; mi++)
#pragma unroll
        for (int ni = 0; ni < 8; ni++)
#pragma unroll
            for (int r = 0; r < 4; r++) acc[mi][ni][r] = 0.f;

    const int T = K / BK;

    auto issue = [&](int t, int buf) {
        const float* Ag = A + (size_t)bm * K + t * BK;
#pragma unroll
        for (int u = 0; u < 8; u++) {
            int i4 = tid + 128 * u;
            int r = i4 >> 3, c4 = i4 & 7;
            uint32_t d = (uint32_t)__cvta_generic_to_shared(
                As + buf * BM * AST + r * AST + c4 * 4);
            cp16(d, Ag + (size_t)r * K + c4 * 4);
        }
        const float* Bg = B + (size_t)(t * BK) * N + bn;
#pragma unroll
        for (int u = 0; u < 8; u++) {
            int i4 = tid + 128 * u;
            int r = i4 >> 5, c4 = i4 & 31;
            uint32_t d = (uint32_t)__cvta_generic_to_shared(
                Bs + buf * BK * BST + r * BST + c4 * 4);
            cp16(d, Bg + (size_t)r * N + c4 * 4);
        }
        CP_COMMIT();
    };

    issue(0, 0);

    int buf = 0;
    for (int t = 0; t < T; t++) {
        if (t + 1 < T) {
            issue(t + 1, buf ^ 1);
            CP_WAIT1();
        } else {
            CP_WAIT0();
        }
        __syncthreads();

        const float* Ab = As + buf * BM * AST;
        const float* Bb = Bs + buf * BK * BST;

#pragma unroll
        for (int ks = 0; ks < 4; ks++) {
            const int kc = ks * 8;
            uint32_t a[4][4], b[8][2];
#pragma unroll
            for (int mi = 0; mi < 4; mi++) {
                int row = wm * 64 + mi * 16 + g;
                a[mi][0] = fau(Ab[row * AST + kc + tg]);
                a[mi][1] = fau(Ab[(row + 8) * AST + kc + tg]);
                a[mi][2] = fau(Ab[row * AST + kc + tg + 4]);
                a[mi][3] = fau(Ab[(row + 8) * AST + kc + tg + 4]);
            }
#pragma unroll
            for (int ni = 0; ni < 8; ni++) {
                int col = wn * 64 + ni * 8 + g;
                b[ni][0] = fau(Bb[(kc + tg) * BST + col]);
                b[ni][1] = fau(Bb[(kc + tg + 4) * BST + col]);
            }
#pragma unroll
            for (int mi = 0; mi < 4; mi++)
#pragma unroll
                for (int ni = 0; ni < 8; ni++)
                    mma_tf32(acc[mi][ni], a[mi][0], a[mi][1], a[mi][2], a[mi][3],
                             b[ni][0], b[ni][1]);
        }
        __syncthreads();
        buf ^= 1;
    }

#pragma unroll
    for (int mi = 0; mi < 4; mi++) {
        int row0 = bm + wm * 64 + mi * 16 + g;
#pragma unroll
        for (int ni = 0; ni < 8; ni++) {
            int col = bn + wn * 64 + ni * 8 + tg * 2;
            float4 v = make_float4(acc[mi][ni][0], acc[mi][ni][1],
                                   acc[mi][ni][2], acc[mi][ni][3]);
            if (round_out) {
                v.x = to_tf32(v.x); v.y = to_tf32(v.y);
                v.z = to_tf32(v.z); v.w = to_tf32(v.w);
            }
            *(float2*)(C + (size_t)row0 * N + col) = make_float2(v.x, v.y);
            *(float2*)(C + (size_t)(row0 + 8) * N + col) = make_float2(v.z, v.w);
        }
    }
}

// ---------------------------------------------------------------------------
// RoPE (in-place, pair-safe), rounds outputs to tf32.
// ---------------------------------------------------------------------------
__global__ void rope_kernel(float* __restrict__ T, const int* __restrict__ pos_ids,
                            int cols, int npairs)
{
    int idx = blockIdx.x * blockDim.x + threadIdx.x;
    if (idx >= npairs) return;
    int half = cols >> 1;
    int row = idx / half;
    int cp = idx - row * half;
    int h = cp >> 6;
    int d = cp & 63;
    int c0 = h * 128 + d;
    float pos = (float)pos_ids[row];
    double inv = pow(10000.0, -((double)d) / 64.0);
    float ang = (float)((double)pos * inv);
    float sn = sinf(ang), cs = cosf(ang);
    float* rowp = T + (size_t)row * cols;
    float x0 = rowp[c0];
    float x1 = rowp[c0 + 64];
    rowp[c0]      = to_tf32(x0 * cs - x1 * sn);
    rowp[c0 + 64] = to_tf32(x1 * cs + x0 * sn);
}

// ---------------------------------------------------------------------------
// Tensor-core flash attention (causal, GQA), tf32 mma.sync.
// CTA = 128 q rows x head x batch; 8 warps x 16 rows; K-tile 64, 2-stage.
// Q fragments live in registers; Q smem region is reused for P.
// ---------------------------------------------------------------------------
#define FQ   128
#define FKT  64
#define QST  132   // %32==4 -> conflict-free Q loads for fragment extraction
#define KST  132   // %32==4 -> K^T b-frag conflict-free
#define VST  136   // %32==8 -> V b-frag conflict-free
#define PST2 68    // %32==4 -> P a-frag conflict-free

#define OFF_K  0
#define OFF_V  (OFF_K + 2 * FKT * KST)          // 16896
#define OFF_QP (OFF_V + 2 * FKT * VST)          // Q tile first, later P
#define OFF_M  (OFF_QP + FQ * QST)              // 2 x FKT mask biases
#define FL_SMEM ((OFF_M + 2 * FKT) * 4)         // 205312 B

#define SCL 0.12751743f   // (1/sqrt(128)) * log2(e)

__global__ void __launch_bounds__(256, 1)
flash_tc(const float* __restrict__ Q, const float* __restrict__ K,
         const float* __restrict__ V, const float* __restrict__ amask,
         float* __restrict__ Oc)
{
    extern __shared__ float sm[];
    float* Ks  = sm + OFF_K;
    float* Vs  = sm + OFF_V;
    float* QPs = sm + OFF_QP;     // Q during prologue, P during mainloop
    float* kmb = sm + OFF_M;

    const int hb = blockIdx.x;
    const int h = hb & 31, b = hb >> 5;
    const int qb = gridDim.y - 1 - blockIdx.y;     // heavy q-blocks first
    const int q0 = qb * FQ;
    const int tid = threadIdx.x;
    const int w = tid >> 5, lane = tid & 31;
    const int g = lane >> 2, tg = lane & 3;
    const int kvh = h >> 2;
    const int myrowmax = q0 + w * 16 + 15;

    float oacc[16][4];
#pragma unroll
    for (int nt = 0; nt < 16; nt++)
#pragma unroll
        for (int r = 0; r < 4; r++) oacc[nt][r] = 0.f;
    float m2[2] = {-1e9f, -1e9f}, l2[2] = {0.f, 0.f};

    // async K/V/mask tile loader (64 x 128 each)
    auto issue = [&](int t, int buf) {
        const float* Kg = K + (size_t)(b * SEQ + t * FKT) * KVW + kvh * HD;
        const float* Vg = V + (size_t)(b * SEQ + t * FKT) * KVW + kvh * HD;
#pragma unroll
        for (int u = 0; u < 8; u++) {
            int i4 = tid + 256 * u;
            int r = i4 >> 5, c4 = i4 & 31;
            uint32_t dk = (uint32_t)__cvta_generic_to_shared(
                Ks + buf * FKT * KST + r * KST + c4 * 4);
            cp16(dk, Kg + (size_t)r * KVW + c4 * 4);
            uint32_t dv = (uint32_t)__cvta_generic_to_shared(
                Vs + buf * FKT * VST + r * VST + c4 * 4);
            cp16(dv, Vg + (size_t)r * KVW + c4 * 4);
        }
        if (tid < FKT)
            kmb[buf * FKT + tid] =
                (amask[b * SEQ + t * FKT + tid] > 0.f) ? 0.f : -1e9f;
        CP_COMMIT();
    };

    issue(0, 0);     // overlap with Q staging

    // Q tile -> smem (plain stores)
    const float* Qg = Q + (size_t)(b * SEQ + q0) * HID + h * HD;
#pragma unroll
    for (int u = 0; u < 16; u++) {
        int i4 = tid + 256 * u;
        int r = i4 >> 5, c4 = i4 & 31;
        float4 v = *(const float4*)(Qg + (size_t)r * HID + c4 * 4);
        QPs[r * QST + c4 * 4 + 0] = v.x;
        QPs[r * QST + c4 * 4 + 1] = v.y;
        QPs[r * QST + c4 * 4 + 2] = v.z;
        QPs[r * QST + c4 * 4 + 3] = v.w;
    }
    __syncthreads();               // Q visible

    // Q fragments -> registers (64 regs)
    uint32_t qa[16][4];
    {
        const float* Qw = QPs + (w * 16) * QST;
#pragma unroll
        for (int ks = 0; ks < 16; ks++) {
            const int kc = ks * 8;
            qa[ks][0] = fau(Qw[g * QST + kc + tg]);
            qa[ks][1] = fau(Qw[(g + 8) * QST + kc + tg]);
            qa[ks][2] = fau(Qw[g * QST + kc + tg + 4]);
            qa[ks][3] = fau(Qw[(g + 8) * QST + kc + tg + 4]);
        }
    }
    __syncthreads();               // all warps done reading Q -> region becomes P

    const int T = 2 * (qb + 1);
    float* Pw = QPs + (w * 16) * PST2;

    for (int t = 0; t < T; t++) {
        const int buf = t & 1;
        if (t + 1 < T) {
            issue(t + 1, buf ^ 1);
            CP_WAIT1();
        } else {
            CP_WAIT0();
        }
        __syncthreads();                         // tile t visible everywhere

        const int k0 = t * FKT;
        if (k0 <= myrowmax) {                    // else fully masked for warp

            // ---- S = Q @ K^T (16 x 64 per warp) ----
            float sacc[8][4];
#pragma unroll
            for (int nt = 0; nt < 8; nt++)
#pragma unroll
                for (int r = 0; r < 4; r++) sacc[nt][r] = 0.f;

            const float* Kb = Ks + buf * FKT * KST;
#pragma unroll
            for (int ks = 0; ks < 16; ks++) {
                const int kc = ks * 8;
#pragma unroll
                for (int nt = 0; nt < 8; nt++) {
                    uint32_t b0 = fau(Kb[(nt * 8 + g) * KST + kc + tg]);
                    uint32_t b1 = fau(Kb[(nt * 8 + g) * KST + kc + tg + 4]);
                    mma_tf32(sacc[nt], qa[ks][0], qa[ks][1], qa[ks][2],
                             qa[ks][3], b0, b1);
                }
            }

            // ---- mask + scale into exp2 domain ----
            const int rowg0 = q0 + w * 16 + g;
            const int rowg1 = rowg0 + 8;
#pragma unroll
            for (int nt = 0; nt < 8; nt++) {
                int cl = nt * 8 + 2 * tg;
                int c0 = k0 + cl;
                float kb0 = kmb[buf * FKT + cl];
                float kb1 = kmb[buf * FKT + cl + 1];
                sacc[nt][0] = (c0     <= rowg0) ? sacc[nt][0] * SCL + kb0 : -1e9f;
                sacc[nt][1] = (c0 + 1 <= rowg0) ? sacc[nt][1] * SCL + kb1 : -1e9f;
                sacc[nt][2] = (c0     <= rowg1) ? sacc[nt][2] * SCL + kb0 : -1e9f;
                sacc[nt][3] = (c0 + 1 <= rowg1) ? sacc[nt][3] * SCL + kb1 : -1e9f;
            }

            // ---- online softmax (exp2 domain) ----
#pragma unroll
            for (int r = 0; r < 2; r++) {
                float pm = -1e30f;
#pragma unroll
                for (int nt = 0; nt < 8; nt++)
                    pm = fmaxf(pm, fmaxf(sacc[nt][2 * r], sacc[nt][2 * r + 1]));
                pm = fmaxf(pm, __shfl_xor_sync(0xffffffffu, pm, 1));
                pm = fmaxf(pm, __shfl_xor_sync(0xffffffffu, pm, 2));
                float mn = fmaxf(m2[r], pm);
                float al = exp2p(m2[r] - mn);
                m2[r] = mn;
                float rs = 0.f;
                float* prow = QPs + (w * 16 + g + 8 * r) * PST2;
#pragma unroll
                for (int nt = 0; nt < 8; nt++) {
                    float p0 = exp2p(sacc[nt][2 * r] - mn);
                    float p1 = exp2p(sacc[nt][2 * r + 1] - mn);
                    rs += p0 + p1;
                    *(float2*)(prow + nt * 8 + 2 * tg) =
                        make_float2(to_tf32(p0), to_tf32(p1));
                }
                rs += __shfl_xor_sync(0xffffffffu, rs, 1);
                rs += __shfl_xor_sync(0xffffffffu, rs, 2);
                l2[r] = l2[r] * al + rs;
                if (al != 1.f) {
#pragma unroll
                    for (int nt = 0; nt < 16; nt++) {
                        oacc[nt][2 * r]     *= al;
                        oacc[nt][2 * r + 1] *= al;
                    }
                }
            }
            __syncwarp();

            // ---- O += P @ V ----
            const float* Vb = Vs + buf * FKT * VST;
#pragma unroll
            for (int ks = 0; ks < 8; ks++) {
                const int kc = ks * 8;
                uint32_t a0 = fau(Pw[g * PST2 + kc + tg]);
                uint32_t a1 = fau(Pw[(g + 8) * PST2 + kc + tg]);
                uint32_t a2 = fau(Pw[g * PST2 + kc + tg + 4]);
                uint32_t a3 = fau(Pw[(g + 8) * PST2 + kc + tg + 4]);
#pragma unroll
                for (int nt = 0; nt < 16; nt++) {
                    uint32_t b0 = fau(Vb[(kc + tg) * VST + nt * 8 + g]);
                    uint32_t b1 = fau(Vb[(kc + tg + 4) * VST + nt * 8 + g]);
                    mma_tf32(oacc[nt], a0, a1, a2, a3, b0, b1);
                }
            }
        }
        __syncthreads();                         // all reads of buf done
    }

    // ---- epilogue ----
    float i0 = 1.f / l2[0], i1 = 1.f / l2[1];
    size_t ro0 = (size_t)(b * SEQ + q0 + w * 16 + g) * HID + h * HD;
    size_t ro1 = ro0 + (size_t)8 * HID;
#pragma unroll
    for (int nt = 0; nt < 16; nt++) {
        int c = nt * 8 + 2 * tg;
        *(float2*)(Oc + ro0 + c) = make_float2(to_tf32(oacc[nt][0] * i0),
                                               to_tf32(oacc[nt][1] * i0));
        *(float2*)(Oc + ro1 + c) = make_float2(to_tf32(oacc[nt][2] * i1),
                                               to_tf32(oacc[nt][3] * i1));
    }
}

// ---------------------------------------------------------------------------
// Launch
// ---------------------------------------------------------------------------
extern "C" void kernel_launch(void* const* d_in, const int* in_sizes, int n_in,
                              void* d_out, int out_size)
{
    const float* hs    = (const float*)d_in[0];
    const float* amask = (const float*)d_in[1];
    const int*   pos   = (const int*)d_in[2];
    const float* Wq    = (const float*)d_in[3];
    const float* Wk    = (const float*)d_in[4];
    const float* Wv    = (const float*)d_in[5];
    const float* Wo    = (const float*)d_in[6];
    float* out = (float*)d_out;

    float *Qp, *Kp, *Vp, *Ap, *Xp, *Wqp, *Wkp, *Wvp, *Wop;
    cudaGetSymbolAddress((void**)&Qp, g_Q);
    cudaGetSymbolAddress((void**)&Kp, g_K);
    cudaGetSymbolAddress((void**)&Vp, g_V);
    cudaGetSymbolAddress((void**)&Ap, g_A);
    cudaGetSymbolAddress((void**)&Xp, g_X);
    cudaGetSymbolAddress((void**)&Wqp, g_Wq);
    cudaGetSymbolAddress((void**)&Wkp, g_Wk);
    cudaGetSymbolAddress((void**)&Wvp, g_Wv);
    cudaGetSymbolAddress((void**)&Wop, g_Wo);

    cudaFuncSetAttribute(tf32gemm, cudaFuncAttributeMaxDynamicSharedMemorySize,
                         GEMM_SMEM);
    cudaFuncSetAttribute(flash_tc, cudaFuncAttributeMaxDynamicSharedMemorySize,
                         FL_SMEM);

    // Round inputs to tf32 (RNA)
    {
        int n;
        n = MROWS * HID / 4;
        round_tf32_kernel<<<(n + 255) / 256, 256>>>(hs, Xp, n);
        n = HID * HID / 4;
        round_tf32_kernel<<<(n + 255) / 256, 256>>>(Wq, Wqp, n);
        round_tf32_kernel<<<(n + 255) / 256, 256>>>(Wo, Wop, n);
        n = HID * KVW / 4;
        round_tf32_kernel<<<(n + 255) / 256, 256>>>(Wk, Wkp, n);
        round_tf32_kernel<<<(n + 255) / 256, 256>>>(Wv, Wvp, n);
    }

    // Projections (tf32 tensor cores); outputs rounded to tf32
    tf32gemm<<<dim3(HID / BN, MROWS / BM), 128, GEMM_SMEM>>>(Xp, Wqp, Qp, MROWS, HID, HID, 1);
    tf32gemm<<<dim3(KVW / BN, MROWS / BM), 128, GEMM_SMEM>>>(Xp, Wkp, Kp, MROWS, KVW, HID, 1);
    tf32gemm<<<dim3(KVW / BN, MROWS / BM), 128, GEMM_SMEM>>>(Xp, Wvp, Vp, MROWS, KVW, HID, 1);

    // RoPE on Q and K
    {
        int npq = MROWS * (HID / 2);
        rope_kernel<<<(npq + 255) / 256, 256>>>(Qp, pos, HID, npq);
        int npk = MROWS * (KVW / 2);
        rope_kernel<<<(npk + 255) / 256, 256>>>(Kp, pos, KVW, npk);
    }

    // Tensor-core flash attention (K-tile 64)
    flash_tc<<<dim3(NHEADS * BATCH, SEQ / FQ), 256, FL_SMEM>>>(Qp, Kp, Vp,
                                                               amask, Ap);

    // Output projection, full fp32 output
    tf32gemm<<<dim3(HID / BN, MROWS / BM), 128, GEMM_SMEM>>>(Ap, Wop, out, MROWS, HID, HID, 0);
}